// round 12
// baseline (speedup 1.0000x reference)
#include <cuda_runtime.h>
#include <cuda_bf16.h>

// x:       (L=2048, B=16) int32   -> x[l*16 + b]
// embed_w: (V=50257, D=1024) fp32 -> w[t*1024 + d]
// out:     (B=16, D=1024, L=2048) fp32 -> out[b*D*L + d*L + l]
// rows with token >= 20 are zero; output scaled by sqrt(8).

#define L_DIM   2048
#define B_DIM   16
#define D_DIM   1024
#define MAXTOK  20
#define SCALE   2.8284271247461903f  // sqrt(8)

#define NBLK    2048
#define TPB     256
#define ZITER   16           // 2048*256*16 = 8388608 float4
#define STRIDE  (1u << 19)   // NBLK*TPB

// Single kernel, no device globals, no cross-block dependencies.
//
// Warp permutation: W = (bid>>4)*128 + wid*16 + (bid&15)  (bijective on 16384).
// idx0 = W*32 + lane:
//   l4 = idx0 & 511  = (bid&15)*32 + lane   -> warp covers one aligned window
//   d  = (idx0>>9)   = (bid>>4)*8  + wid    -> warp-uniform, iteration-invariant
//   b  = iteration k (STRIDE = 2^19 bumps bit 19+ only) -> all 16 b per thread
// Store stream: iteration k writes the contiguous 8MB slab [k*8MB,(k+1)*8MB),
// each warp 512B contiguous — the proven LTS-ceiling pattern.
__global__ void __launch_bounds__(TPB) fused_kernel(
    const int* __restrict__ x,
    const float* __restrict__ w,
    float4* __restrict__ out)
{
    __shared__ unsigned s_parts[8];

    const int tid  = threadIdx.x;
    const int wid  = tid >> 5;
    const int lane = tid & 31;
    const int bid  = blockIdx.x;
    const int wi   = bid & 15;              // this block's l4 window (0..15)

    const unsigned W    = ((unsigned)(bid >> 4) << 7) | ((unsigned)wid << 4) | (unsigned)wi;
    const unsigned idx0 = (W << 5) | (unsigned)lane;

    // ---- window tokens: 2 coalesced int4 / thread (8 KB per block, L2-hot;
    //      128 blocks share each window -> 16 MB total, half of R11) ----
    const int4* src = (const int4*)x + wi * 512;     // 2048 tokens = 512 int4
    int4 v1 = __ldg(src + tid);
    int4 v2 = __ldg(src + tid + 256);

    // ---- unconditional zero sweep (proven LTS-ceiling pattern) ----
    const float4 z = make_float4(0.f, 0.f, 0.f, 0.f);
    unsigned idx = idx0;
    #pragma unroll
    for (int k = 0; k < ZITER; k++) {
        out[idx] = z;
        idx += STRIDE;
    }

    // ---- build window's 32-bit detail word (bit g = l4-group wi*32+g hit) --
    // int4 j covers relative group j>>4; warp reads j in [32wid,32wid+32)
    // and [256+32wid, ...): groups {2wid,2wid+1} and {16+2wid,17+2wid}.
    int m1 = min(min(v1.x, v1.y), min(v1.z, v1.w));
    int m2 = min(min(v2.x, v2.y), min(v2.z, v2.w));
    unsigned bal1 = __ballot_sync(0xFFFFFFFFu, m1 < MAXTOK);
    unsigned bal2 = __ballot_sync(0xFFFFFFFFu, m2 < MAXTOK);
    unsigned part = 0;
    part |= ((bal1 & 0xFFFFu) ? 1u : 0u) << (2 * wid);
    part |= ((bal1 >> 16)     ? 1u : 0u) << (2 * wid + 1);
    part |= ((bal2 & 0xFFFFu) ? 1u : 0u) << (16 + 2 * wid);
    part |= ((bal2 >> 16)     ? 1u : 0u) << (17 + 2 * wid);
    if (lane == 0) s_parts[wid] = part;
    __syncthreads();   // publishes s_parts AND orders fixup after zero stores

    unsigned word = s_parts[0] | s_parts[1] | s_parts[2] | s_parts[3]
                  | s_parts[4] | s_parts[5] | s_parts[6] | s_parts[7];
    if (word == 0) return;                  // block-uniform exit (~45%)

    // ---- cooperative fixup: per set bit, 32 lanes x 2 rounds cover 4l x 16b
    const int d     = (int)(W >> 4);        // warp-uniform (== (idx0>>9)&1023)
    const int b     = lane & 15;
    const int l_off = lane >> 4;            // 0..1
    float* outf = (float*)out;

    while (word) {                          // uniform loop, ~1 iteration
        int g = __ffs(word) - 1;
        word &= word - 1;
        int l_base = (wi * 32 + g) << 2;
        #pragma unroll
        for (int r = 0; r < 2; r++) {
            int l = l_base + l_off + 2 * r;
            int t = __ldg(x + l * B_DIM + b);   // 32 lanes: 128B L2-hot
            if (t < MAXTOK) {
                outf[(size_t)b * (D_DIM * L_DIM) + (size_t)d * L_DIM + l] =
                    __ldg(w + (size_t)t * D_DIM + d) * SCALE;
            }
        }
    }
}

extern "C" void kernel_launch(void* const* d_in, const int* in_sizes, int n_in,
                              void* d_out, int out_size)
{
    const int*   x = (const int*)d_in[0];
    const float* w = (const float*)d_in[1];
    fused_kernel<<<NBLK, TPB>>>(x, w, (float4*)d_out);
}